// round 5
// baseline (speedup 1.0000x reference)
#include <cuda_runtime.h>
#include <cuda_bf16.h>
#include <cstdint>

#define N_ROWS   65536
#define K_CENT   512
#define D_DIM    1024
#define TILE_M   128
#define CH_N     256          // centers per chunk
#define NCHUNK   2
#define KSLAB    64
#define NSLABS   (D_DIM / KSLAB)   // 16
#define TAU_F    0.1f
#define EPS_F    1e-8f

// Normalized centers in bf16 (1/||c|| folded in), row-major [K_CENT][D_DIM]
__device__ __align__(16) __nv_bfloat16 g_cbf[K_CENT * D_DIM];
// Per-chunk partial softmax stats
__device__ float g_pm[NCHUNK * N_ROWS];
__device__ float g_ps[NCHUNK * N_ROWS];
__device__ float g_plv[NCHUNK * N_ROWS];

// ---------------- helpers ----------------
__device__ __forceinline__ uint32_t smem_u32(const void* p) {
    uint32_t a;
    asm("{ .reg .u64 t; cvta.to.shared.u64 t, %1; cvt.u32.u64 %0, t; }" : "=r"(a) : "l"(p));
    return a;
}
#define SWZ(o) ((o) ^ ((((uint32_t)(o)) >> 3) & 0x70u))

__device__ __forceinline__ void cp16(uint32_t dst, const void* src) {
    asm volatile("cp.async.cg.shared.global [%0], [%1], 16;"
                 :: "r"(dst), "l"(__cvta_generic_to_global(src)) : "memory");
}
#define CP_COMMIT() asm volatile("cp.async.commit_group;" ::: "memory")
#define CP_WAIT1()  asm volatile("cp.async.wait_group 1;" ::: "memory")

__device__ __forceinline__ void ldsm4(uint32_t* r, uint32_t addr) {
    asm volatile("ldmatrix.sync.aligned.m8n8.x4.shared.b16 {%0,%1,%2,%3}, [%4];"
                 : "=r"(r[0]), "=r"(r[1]), "=r"(r[2]), "=r"(r[3]) : "r"(addr));
}

__device__ __forceinline__ void mma16816(float* d, const uint32_t* a,
                                         uint32_t b0, uint32_t b1) {
    asm volatile(
        "mma.sync.aligned.m16n8k16.row.col.f32.bf16.bf16.f32 "
        "{%0,%1,%2,%3}, {%4,%5,%6,%7}, {%8,%9}, {%0,%1,%2,%3};"
        : "+f"(d[0]), "+f"(d[1]), "+f"(d[2]), "+f"(d[3])
        : "r"(a[0]), "r"(a[1]), "r"(a[2]), "r"(a[3]), "r"(b0), "r"(b1));
}

__device__ __forceinline__ uint32_t pk(float x, float y) {
    __nv_bfloat162 h = __floats2bfloat162_rn(x, y);
    return *reinterpret_cast<uint32_t*>(&h);
}

// ---------------- Kernel 1: normalize centers -> bf16, zero out ----------------
__global__ void __launch_bounds__(256) prep_centers_kernel(const float* __restrict__ centers,
                                                           float* __restrict__ out) {
    __shared__ float wss[8];
    const int row = blockIdx.x;
    const int t = threadIdx.x;

    float4 v = reinterpret_cast<const float4*>(centers + (size_t)row * D_DIM)[t];
    float ss = v.x * v.x + v.y * v.y + v.z * v.z + v.w * v.w;
#pragma unroll
    for (int o = 16; o; o >>= 1) ss += __shfl_xor_sync(0xFFFFFFFFu, ss, o);
    if ((t & 31) == 0) wss[t >> 5] = ss;
    __syncthreads();
    if (t < 32) {
        float x = (t < 8) ? wss[t] : 0.f;
#pragma unroll
        for (int o = 4; o; o >>= 1) x += __shfl_xor_sync(0xFFFFFFFFu, x, o);
        if (t == 0) wss[0] = x;
    }
    __syncthreads();
    const float sc = 1.0f / fmaxf(sqrtf(wss[0]), EPS_F);

    __nv_bfloat162* orow = reinterpret_cast<__nv_bfloat162*>(g_cbf + (size_t)row * D_DIM);
    orow[t * 2]     = __floats2bfloat162_rn(v.x * sc, v.y * sc);
    orow[t * 2 + 1] = __floats2bfloat162_rn(v.z * sc, v.w * sc);

    if (row == 0 && t == 0) out[0] = 0.f;
}

// ---------------- Kernel 2: fused GEMM, 256 thr, pipelined fp32->bf16 convert ----------------
// grid = 1024: mtile = bid>>1 (128 rows), chunk = bid&1 (256 centers)
// 8 warps, warp grid 2(m) x 4(n): warp tile 64 rows x 64 cols, acc 128 regs
// SMEM (1024-aligned base):
//   A32 3 x 32768 @ 0       fp32 slab staging (row*256B, XOR-chunk)
//   B   3 x 32768 @ 98304   bf16 SW128
//   ABF 2 x 16384 @ 196608  bf16 A ldsm tile, SW128   -> end 229376
#define A32_STG   32768u
#define B_STG     32768u
#define OFF_A32   0u
#define OFF_B     98304u
#define OFF_ABF   196608u
#define SMEM_DYN  (229376 + 1024)
// post-loop stats (alias A32)
#define OFF_SS    0u        // 256 f
#define OFF_SCALE 1024u     // 128 f
#define OFF_MM    2048u     // 512 f
#define OFF_MS    4096u     // 512 f
#define OFF_MLV   6144u     // 512 f

__global__ void __launch_bounds__(256, 1)
gemm_chunk_kernel(const float* __restrict__ emb,
                  const long long* __restrict__ labels) {
    extern __shared__ uint8_t dyn[];
    const uint32_t sb = smem_u32(dyn);
    const uint32_t base = (sb + 1023u) & ~1023u;
    uint8_t* gbase = dyn + (base - sb);

    float* ss_arr = reinterpret_cast<float*>(gbase + OFF_SS);
    float* sc_arr = reinterpret_cast<float*>(gbase + OFF_SCALE);
    float* sm_m   = reinterpret_cast<float*>(gbase + OFF_MM);
    float* sm_s   = reinterpret_cast<float*>(gbase + OFF_MS);
    float* sm_lv  = reinterpret_cast<float*>(gbase + OFF_MLV);

    const int t     = threadIdx.x;
    const int lane  = t & 31;
    const int wid   = t >> 5;
    const int wm    = wid & 1;    // 64-row slice
    const int wn    = wid >> 1;   // 64-col slice
    const int bid   = blockIdx.x;
    const int mtile = bid >> 1;
    const int chunk = bid & 1;
    const int row0  = mtile * TILE_M;

    // ---- A mapping: thread owns 8 consecutive 16B chunks (32 floats) of one row ----
    const int ar = t >> 1;            // 0..127
    const int ah = t & 1;             // half of the 64-float slab
    const float* agp = emb + (size_t)(row0 + ar) * D_DIM + ah * 32;
    uint32_t a32_off[8];
#pragma unroll
    for (int i = 0; i < 8; ++i) {
        const int c = ah * 8 + i;     // chunk index 0..15 within row
        a32_off[i] = (uint32_t)(ar * 256 + ((c ^ (ar & 15)) << 4));
    }
    uint32_t abf_sw[4];
#pragma unroll
    for (int j = 0; j < 4; ++j)
        abf_sw[j] = SWZ((uint32_t)(ar * 128 + ah * 64 + j * 16));

    // ---- B mapping: thread owns 8 chunks, rows br + i*32 ----
    const int br = t >> 3, bo = t & 7;
    const __nv_bfloat16* bgp = g_cbf + (size_t)(chunk * CH_N + br) * D_DIM + bo * 8;

    auto issueA = [&](int kb, int stg) {
        const uint32_t Ad = base + OFF_A32 + (uint32_t)stg * A32_STG;
        const float* s = agp + kb * KSLAB;
#pragma unroll
        for (int i = 0; i < 8; ++i) cp16(Ad + a32_off[i], s + i * 4);
    };
    auto issueB = [&](int kb, int stg) {
        const uint32_t Bd = base + OFF_B + (uint32_t)stg * B_STG;
        const __nv_bfloat16* s = bgp + kb * KSLAB;
#pragma unroll
        for (int i = 0; i < 8; ++i)
            cp16(Bd + SWZ((uint32_t)((br + i * 32) * 128 + bo * 16)),
                 s + (size_t)(i * 32) * D_DIM);
    };

    float myss = 0.f;
    auto convertA = [&](int kb) {   // A32 stage kb%3 -> ABF[kb&1], accumulate sumsq
        const uint32_t A32b = base + OFF_A32 + (uint32_t)(kb % 3) * A32_STG;
        const uint32_t Abf  = base + OFF_ABF + (uint32_t)(kb & 1) * 16384u;
#pragma unroll
        for (int j = 0; j < 4; ++j) {
            float4 f0, f1;
            asm volatile("ld.shared.v4.f32 {%0,%1,%2,%3}, [%4];"
                         : "=f"(f0.x), "=f"(f0.y), "=f"(f0.z), "=f"(f0.w)
                         : "r"(A32b + a32_off[2 * j]));
            asm volatile("ld.shared.v4.f32 {%0,%1,%2,%3}, [%4];"
                         : "=f"(f1.x), "=f"(f1.y), "=f"(f1.z), "=f"(f1.w)
                         : "r"(A32b + a32_off[2 * j + 1]));
            myss += f0.x * f0.x + f0.y * f0.y + f0.z * f0.z + f0.w * f0.w
                  + f1.x * f1.x + f1.y * f1.y + f1.z * f1.z + f1.w * f1.w;
            asm volatile("st.shared.v4.b32 [%0], {%1,%2,%3,%4};"
                         :: "r"(Abf + abf_sw[j]),
                            "r"(pk(f0.x, f0.y)), "r"(pk(f0.z, f0.w)),
                            "r"(pk(f1.x, f1.y)), "r"(pk(f1.z, f1.w)));
        }
    };

    float acc[4][8][4];
#pragma unroll
    for (int am = 0; am < 4; ++am)
#pragma unroll
        for (int an = 0; an < 8; ++an)
#pragma unroll
            for (int k = 0; k < 4; ++k) acc[am][an][k] = 0.f;

    // ---- prologue ----
    issueA(0, 0); issueB(0, 0); CP_COMMIT();
    issueA(1, 1); issueB(1, 1); CP_COMMIT();
    CP_WAIT1();                 // group 0 done
    __syncthreads();
    convertA(0);                // ABF[0]
    __syncthreads();

    const int rlow = lane & 15;
    const int bhi  = (lane >> 4) * 16;

#pragma unroll 1
    for (int kb = 0; kb < NSLABS; ++kb) {
        // 1. issue slab kb+2
        if (kb + 2 < NSLABS) {
            const int ns = (kb + 2) % 3;
            issueA(kb + 2, ns);
            issueB(kb + 2, ns);
        }
        CP_COMMIT();
        // 2. slab kb+1 (A32+B) and B(kb) resident
        CP_WAIT1();

        // 3. convert slab kb+1 (off critical path; overlaps MMA issue below)
        if (kb + 1 < NSLABS) convertA(kb + 1);

        // 4. MMAs on ABF[kb&1] and B stage kb%3
        const uint32_t Abf = base + OFF_ABF + (uint32_t)(kb & 1) * 16384u;
        const uint32_t Bb  = base + OFF_B + (uint32_t)(kb % 3) * B_STG;
#pragma unroll
        for (int ks = 0; ks < 4; ++ks) {
            const uint32_t byt = (uint32_t)(ks * 32 + bhi);
            uint32_t af[4][4], bf[4][4];
#pragma unroll
            for (int am = 0; am < 4; ++am)
                ldsm4(af[am], Abf + SWZ((uint32_t)((wm * 64 + am * 16 + rlow) * 128) + byt));
#pragma unroll
            for (int p = 0; p < 4; ++p)
                ldsm4(bf[p], Bb + SWZ((uint32_t)((wn * 64 + p * 16 + rlow) * 128) + byt));
#pragma unroll
            for (int am = 0; am < 4; ++am)
#pragma unroll
                for (int p = 0; p < 4; ++p) {
                    mma16816(acc[am][2 * p],     af[am], bf[p][0], bf[p][2]);
                    mma16816(acc[am][2 * p + 1], af[am], bf[p][1], bf[p][3]);
                }
        }
        // 5. single barrier: protects ABF[(kb+1)&1] writes vs next ldsm,
        //    and stage reuse for A32/B issued next iteration
        __syncthreads();
    }

    // ---- row scales from fp32 sumsq ----
    ss_arr[t] = myss;
    __syncthreads();
    if (t < TILE_M) {
        float s2 = ss_arr[2 * t] + ss_arr[2 * t + 1];
        sc_arr[t] = 1.0f / (fmaxf(sqrtf(s2), EPS_F) * TAU_F);
    }
    __syncthreads();

    // ---- per-warp partial softmax over its 64 cols ----
    const int ql = lane >> 2, qc = lane & 3;
#pragma unroll
    for (int am = 0; am < 4; ++am) {
#pragma unroll
        for (int h = 0; h < 2; ++h) {
            const int r = wm * 64 + am * 16 + ql + 8 * h;
            const float sc = sc_arr[r];
            const int lc = (int)labels[row0 + r];

            float m = -1e30f;
            float v[16];
#pragma unroll
            for (int an = 0; an < 8; ++an)
#pragma unroll
                for (int e = 0; e < 2; ++e) {
                    float x = acc[am][an][2 * h + e] * sc;
                    v[an * 2 + e] = x;
                    m = fmaxf(m, x);
                }
            m = fmaxf(m, __shfl_xor_sync(0xFFFFFFFFu, m, 1));
            m = fmaxf(m, __shfl_xor_sync(0xFFFFFFFFu, m, 2));

            float s = 0.f, lv = 0.f;
#pragma unroll
            for (int an = 0; an < 8; ++an)
#pragma unroll
                for (int e = 0; e < 2; ++e) {
                    s += __expf(v[an * 2 + e] - m);
                    const int col = chunk * CH_N + wn * 64 + an * 8 + qc * 2 + e;
                    if (col == lc) lv = v[an * 2 + e];
                }
            s  += __shfl_xor_sync(0xFFFFFFFFu, s, 1);
            s  += __shfl_xor_sync(0xFFFFFFFFu, s, 2);
            lv += __shfl_xor_sync(0xFFFFFFFFu, lv, 1);
            lv += __shfl_xor_sync(0xFFFFFFFFu, lv, 2);

            if (qc == 0) {
                sm_m[wn * 128 + r]  = m;
                sm_s[wn * 128 + r]  = s;
                sm_lv[wn * 128 + r] = lv;
            }
        }
    }
    __syncthreads();

    // ---- merge 4 warp-columns, write chunk partials ----
    if (t < TILE_M) {
        float M = -1e30f;
#pragma unroll
        for (int w = 0; w < 4; ++w) M = fmaxf(M, sm_m[w * 128 + t]);
        float S = 0.f, LV = 0.f;
#pragma unroll
        for (int w = 0; w < 4; ++w) {
            S  += sm_s[w * 128 + t] * __expf(sm_m[w * 128 + t] - M);
            LV += sm_lv[w * 128 + t];
        }
        const int gr = row0 + t;
        g_pm[chunk * N_ROWS + gr]  = M;
        g_ps[chunk * N_ROWS + gr]  = S;
        g_plv[chunk * N_ROWS + gr] = LV;
    }
}

// ---------------- Kernel 3: finalize ----------------
__global__ void __launch_bounds__(256) finalize_kernel(float* __restrict__ out) {
    __shared__ float wsum[8];
    const int r = blockIdx.x * 256 + threadIdx.x;

    const float m0 = g_pm[r],           m1 = g_pm[N_ROWS + r];
    const float s0 = g_ps[r],           s1 = g_ps[N_ROWS + r];
    const float lv = g_plv[r] + g_plv[N_ROWS + r];
    const float M  = fmaxf(m0, m1);
    const float S  = s0 * expf(m0 - M) + s1 * expf(m1 - M);
    float loss = (M + logf(S)) - lv;

#pragma unroll
    for (int o = 16; o; o >>= 1) loss += __shfl_xor_sync(0xFFFFFFFFu, loss, o);
    const int t = threadIdx.x;
    if ((t & 31) == 0) wsum[t >> 5] = loss;
    __syncthreads();
    if (t < 32) {
        float x = (t < 8) ? wsum[t] : 0.f;
#pragma unroll
        for (int o = 4; o; o >>= 1) x += __shfl_xor_sync(0xFFFFFFFFu, x, o);
        if (t == 0) atomicAdd(out, x * (1.0f / (float)N_ROWS));
    }
}

// ---------------- Launch ----------------
extern "C" void kernel_launch(void* const* d_in, const int* in_sizes, int n_in,
                              void* d_out, int out_size) {
    const float* emb       = (const float*)d_in[0];
    const float* centers   = (const float*)d_in[1];
    const long long* label = (const long long*)d_in[2];
    float* out             = (float*)d_out;

    cudaFuncSetAttribute(gemm_chunk_kernel, cudaFuncAttributeMaxDynamicSharedMemorySize, SMEM_DYN);

    prep_centers_kernel<<<K_CENT, 256>>>(centers, out);
    gemm_chunk_kernel<<<(N_ROWS / TILE_M) * NCHUNK, 256, SMEM_DYN>>>(emb, label);
    finalize_kernel<<<N_ROWS / 256, 256>>>(out);
}

// round 6
// speedup vs baseline: 1.4207x; 1.4207x over previous
#include <cuda_runtime.h>
#include <cuda_bf16.h>
#include <cstdint>

#define N_ROWS   65536
#define K_CENT   512
#define D_DIM    1024
#define TILE_M   128
#define CH_N     256          // centers per chunk
#define NCHUNK   2
#define KSLAB    64
#define NSLABS   (D_DIM / KSLAB)   // 16
#define TAU_F    0.1f
#define EPS_F    1e-8f

// Normalized centers in bf16 (1/||c|| folded in), row-major [K_CENT][D_DIM]
__device__ __align__(16) __nv_bfloat16 g_cbf[K_CENT * D_DIM];
// Normalized embeddings in bf16 with 1/(||e||*tau) folded in, [N_ROWS][D_DIM]
__device__ __align__(16) __nv_bfloat16 g_ebf[(size_t)N_ROWS * D_DIM];
// Per-chunk partial softmax stats
__device__ float g_pm[NCHUNK * N_ROWS];
__device__ float g_ps[NCHUNK * N_ROWS];
__device__ float g_plv[NCHUNK * N_ROWS];

// ---------------- helpers ----------------
__device__ __forceinline__ uint32_t smem_u32(const void* p) {
    uint32_t a;
    asm("{ .reg .u64 t; cvta.to.shared.u64 t, %1; cvt.u32.u64 %0, t; }" : "=r"(a) : "l"(p));
    return a;
}
#define SWZ(o) ((o) ^ ((((uint32_t)(o)) >> 3) & 0x70u))

__device__ __forceinline__ void cp16(uint32_t dst, const void* src) {
    asm volatile("cp.async.cg.shared.global [%0], [%1], 16;"
                 :: "r"(dst), "l"(__cvta_generic_to_global(src)) : "memory");
}
#define CP_COMMIT() asm volatile("cp.async.commit_group;" ::: "memory")
#define CP_WAIT2()  asm volatile("cp.async.wait_group 2;" ::: "memory")

__device__ __forceinline__ void ldsm4(uint32_t* r, uint32_t addr) {
    asm volatile("ldmatrix.sync.aligned.m8n8.x4.shared.b16 {%0,%1,%2,%3}, [%4];"
                 : "=r"(r[0]), "=r"(r[1]), "=r"(r[2]), "=r"(r[3]) : "r"(addr));
}

__device__ __forceinline__ void mma16816(float* d, const uint32_t* a,
                                         uint32_t b0, uint32_t b1) {
    asm volatile(
        "mma.sync.aligned.m16n8k16.row.col.f32.bf16.bf16.f32 "
        "{%0,%1,%2,%3}, {%4,%5,%6,%7}, {%8,%9}, {%0,%1,%2,%3};"
        : "+f"(d[0]), "+f"(d[1]), "+f"(d[2]), "+f"(d[3])
        : "r"(a[0]), "r"(a[1]), "r"(a[2]), "r"(a[3]), "r"(b0), "r"(b1));
}

__device__ __forceinline__ uint32_t pk(float x, float y) {
    __nv_bfloat162 h = __floats2bfloat162_rn(x, y);
    return *reinterpret_cast<uint32_t*>(&h);
}

// ---------------- Kernel 1: normalize centers -> bf16, zero out ----------------
__global__ void __launch_bounds__(256) prep_centers_kernel(const float* __restrict__ centers,
                                                           float* __restrict__ out) {
    __shared__ float wss[8];
    const int row = blockIdx.x;
    const int t = threadIdx.x;

    float4 v = reinterpret_cast<const float4*>(centers + (size_t)row * D_DIM)[t];
    float ss = v.x * v.x + v.y * v.y + v.z * v.z + v.w * v.w;
#pragma unroll
    for (int o = 16; o; o >>= 1) ss += __shfl_xor_sync(0xFFFFFFFFu, ss, o);
    if ((t & 31) == 0) wss[t >> 5] = ss;
    __syncthreads();
    if (t < 32) {
        float x = (t < 8) ? wss[t] : 0.f;
#pragma unroll
        for (int o = 4; o; o >>= 1) x += __shfl_xor_sync(0xFFFFFFFFu, x, o);
        if (t == 0) wss[0] = x;
    }
    __syncthreads();
    const float sc = 1.0f / fmaxf(sqrtf(wss[0]), EPS_F);

    __nv_bfloat162* orow = reinterpret_cast<__nv_bfloat162*>(g_cbf + (size_t)row * D_DIM);
    orow[t * 2]     = __floats2bfloat162_rn(v.x * sc, v.y * sc);
    orow[t * 2 + 1] = __floats2bfloat162_rn(v.z * sc, v.w * sc);

    if (row == 0 && t == 0) out[0] = 0.f;
}

// ---------------- Kernel 1b: embeddings -> bf16 with 1/(||e||*tau) folded ----------------
// warp per row; 8 warps/block; grid = N_ROWS/8
__global__ void __launch_bounds__(256) prep_emb_kernel(const float* __restrict__ emb) {
    const int lane = threadIdx.x & 31;
    const int wrp  = threadIdx.x >> 5;
    const int row  = blockIdx.x * 8 + wrp;

    const float4* src = reinterpret_cast<const float4*>(emb + (size_t)row * D_DIM);
    float4 v[8];
    float ss = 0.f;
#pragma unroll
    for (int j = 0; j < 8; ++j) {
        v[j] = src[lane + j * 32];
        ss += v[j].x * v[j].x + v[j].y * v[j].y + v[j].z * v[j].z + v[j].w * v[j].w;
    }
#pragma unroll
    for (int o = 16; o; o >>= 1) ss += __shfl_xor_sync(0xFFFFFFFFu, ss, o);
    const float sc = 1.0f / (fmaxf(sqrtf(ss), EPS_F) * TAU_F);

    uint2* dst = reinterpret_cast<uint2*>(g_ebf + (size_t)row * D_DIM);
#pragma unroll
    for (int j = 0; j < 8; ++j) {
        uint2 o;
        o.x = pk(v[j].x * sc, v[j].y * sc);
        o.y = pk(v[j].z * sc, v[j].w * sc);
        dst[lane + j * 32] = o;
    }
}

// ---------------- Kernel 2: GEMM chunk (mma.sync bf16) + partial softmax ----------------
// grid = 1024: mtile = bid>>1 (128 rows), chunk = bid&1 (256 centers)
// 512 threads = 16 warps, warp grid 4(m) x 4(n): warp tile 32 rows x 64 cols
// SMEM (1024-aligned base), 4-stage pipeline, ONE barrier per slab:
#define A_STG     16384u
#define B_STG     32768u
#define OFF_A     0u              // 4 x 16384 = 65536
#define OFF_B     65536u          // 4 x 32768 = 131072 -> end 196608
#define OFF_MM    196608u         // 512 f = 2048
#define OFF_MS    198656u
#define OFF_MLV   200704u         // end 202752
#define SMEM_DYN  (202752 + 1024)

__global__ void __launch_bounds__(512, 1)
gemm_chunk_kernel(const long long* __restrict__ labels) {
    extern __shared__ uint8_t dyn[];
    const uint32_t sb = smem_u32(dyn);
    const uint32_t base = (sb + 1023u) & ~1023u;
    uint8_t* gbase = dyn + (base - sb);

    float* sm_m  = reinterpret_cast<float*>(gbase + OFF_MM);
    float* sm_s  = reinterpret_cast<float*>(gbase + OFF_MS);
    float* sm_lv = reinterpret_cast<float*>(gbase + OFF_MLV);

    const int t     = threadIdx.x;
    const int lane  = t & 31;
    const int wid   = t >> 5;
    const int wm    = wid & 3;    // 32-row slice
    const int wn    = wid >> 2;   // 64-col slice
    const int bid   = blockIdx.x;
    const int mtile = bid >> 1;
    const int chunk = bid & 1;
    const int row0  = mtile * TILE_M;

    // loader mappings (16B chunks): c -> row = c>>3, off8 = c&7
    const int ar = t >> 3, ao = t & 7;   // A: 1024 chunks, 2 per thread (stride 512 -> +64 rows)
    const uint32_t a_sw0 = SWZ((uint32_t)(ar * 128 + ao * 16));
    const uint32_t a_sw1 = SWZ((uint32_t)((ar + 64) * 128 + ao * 16));
    const __nv_bfloat16* agp = g_ebf + (size_t)(row0 + ar) * D_DIM + ao * 8;
    const __nv_bfloat16* bgp = g_cbf + (size_t)(chunk * CH_N + ar) * D_DIM + ao * 8;

    auto issueA = [&](int kb, int stg) {
        const uint32_t Ad = base + OFF_A + (uint32_t)stg * A_STG;
        const __nv_bfloat16* s = agp + kb * KSLAB;
        cp16(Ad + a_sw0, s);
        cp16(Ad + a_sw1, s + (size_t)64 * D_DIM);
    };
    auto issueB = [&](int kb, int stg) {
        const uint32_t Bd = base + OFF_B + (uint32_t)stg * B_STG;
        const __nv_bfloat16* s = bgp + kb * KSLAB;
#pragma unroll
        for (int i = 0; i < 4; ++i) {
            cp16(Bd + SWZ((uint32_t)((ar + i * 64) * 128 + ao * 16)),
                 s + (size_t)(i * 64) * D_DIM);
        }
    };

    float c[2][8][4];
#pragma unroll
    for (int am = 0; am < 2; ++am)
#pragma unroll
        for (int an = 0; an < 8; ++an)
#pragma unroll
            for (int k = 0; k < 4; ++k) c[am][an][k] = 0.f;

    // ---- prologue: stages 0..2 in flight ----
    issueA(0, 0); issueB(0, 0); CP_COMMIT();
    issueA(1, 1); issueB(1, 1); CP_COMMIT();
    issueA(2, 2); issueB(2, 2); CP_COMMIT();

    const int rlow = lane & 15;
    const int bhi  = (lane >> 4) * 16;

#pragma unroll 1
    for (int kb = 0; kb < NSLABS; ++kb) {
        const int stg = kb & 3;
        const uint32_t Ab = base + OFF_A + (uint32_t)stg * A_STG;
        const uint32_t Bb = base + OFF_B + (uint32_t)stg * B_STG;

        CP_WAIT2();              // slab kb resident (2 groups still pending)
        __syncthreads();         // all warps past slab kb-1's ldsm -> stage reuse safe

        if (kb + 3 < NSLABS) {
            const int ns = (kb + 3) & 3;
            issueA(kb + 3, ns);
            issueB(kb + 3, ns);
        }
        CP_COMMIT();             // one group per iteration keeps wait_group 2 aligned

#pragma unroll
        for (int ks = 0; ks < 4; ++ks) {
            const uint32_t byt = (uint32_t)(ks * 32 + bhi);
            uint32_t af[2][4], bf[4][4];
#pragma unroll
            for (int am = 0; am < 2; ++am)
                ldsm4(af[am], Ab + SWZ((uint32_t)((wm * 32 + am * 16 + rlow) * 128) + byt));
#pragma unroll
            for (int p = 0; p < 4; ++p)
                ldsm4(bf[p], Bb + SWZ((uint32_t)((wn * 64 + p * 16 + rlow) * 128) + byt));
#pragma unroll
            for (int am = 0; am < 2; ++am)
#pragma unroll
                for (int p = 0; p < 4; ++p) {
                    mma16816(c[am][2 * p],     af[am], bf[p][0], bf[p][2]);
                    mma16816(c[am][2 * p + 1], af[am], bf[p][1], bf[p][3]);
                }
        }
        // no trailing barrier: next iteration's CP_WAIT2 + __syncthreads covers reuse
    }
    __syncthreads();

    // ---- per-warp partial softmax over its 64 cols (scale pre-folded) ----
    const int ql = lane >> 2, qc = lane & 3;
#pragma unroll
    for (int am = 0; am < 2; ++am) {
#pragma unroll
        for (int h = 0; h < 2; ++h) {
            const int r = wm * 32 + am * 16 + ql + 8 * h;
            const int lc = (int)labels[row0 + r];

            float m = -1e30f;
            float v[16];
#pragma unroll
            for (int an = 0; an < 8; ++an)
#pragma unroll
                for (int e = 0; e < 2; ++e) {
                    float x = c[am][an][2 * h + e];
                    v[an * 2 + e] = x;
                    m = fmaxf(m, x);
                }
            m = fmaxf(m, __shfl_xor_sync(0xFFFFFFFFu, m, 1));
            m = fmaxf(m, __shfl_xor_sync(0xFFFFFFFFu, m, 2));

            float s = 0.f, lv = 0.f;
#pragma unroll
            for (int an = 0; an < 8; ++an)
#pragma unroll
                for (int e = 0; e < 2; ++e) {
                    s += __expf(v[an * 2 + e] - m);
                    const int col = chunk * CH_N + wn * 64 + an * 8 + qc * 2 + e;
                    if (col == lc) lv = v[an * 2 + e];
                }
            s  += __shfl_xor_sync(0xFFFFFFFFu, s, 1);
            s  += __shfl_xor_sync(0xFFFFFFFFu, s, 2);
            lv += __shfl_xor_sync(0xFFFFFFFFu, lv, 1);
            lv += __shfl_xor_sync(0xFFFFFFFFu, lv, 2);

            if (qc == 0) {
                sm_m[wn * 128 + r]  = m;
                sm_s[wn * 128 + r]  = s;
                sm_lv[wn * 128 + r] = lv;
            }
        }
    }
    __syncthreads();

    // ---- merge 4 warp-columns, write chunk partials ----
    if (t < TILE_M) {
        float M = -1e30f;
#pragma unroll
        for (int w = 0; w < 4; ++w) M = fmaxf(M, sm_m[w * 128 + t]);
        float S = 0.f, LV = 0.f;
#pragma unroll
        for (int w = 0; w < 4; ++w) {
            S  += sm_s[w * 128 + t] * __expf(sm_m[w * 128 + t] - M);
            LV += sm_lv[w * 128 + t];
        }
        const int gr = row0 + t;
        g_pm[chunk * N_ROWS + gr]  = M;
        g_ps[chunk * N_ROWS + gr]  = S;
        g_plv[chunk * N_ROWS + gr] = LV;
    }
}

// ---------------- Kernel 3: finalize ----------------
__global__ void __launch_bounds__(256) finalize_kernel(float* __restrict__ out) {
    __shared__ float wsum[8];
    const int r = blockIdx.x * 256 + threadIdx.x;

    const float m0 = g_pm[r],           m1 = g_pm[N_ROWS + r];
    const float s0 = g_ps[r],           s1 = g_ps[N_ROWS + r];
    const float lv = g_plv[r] + g_plv[N_ROWS + r];
    const float M  = fmaxf(m0, m1);
    const float S  = s0 * expf(m0 - M) + s1 * expf(m1 - M);
    float loss = (M + logf(S)) - lv;

#pragma unroll
    for (int o = 16; o; o >>= 1) loss += __shfl_xor_sync(0xFFFFFFFFu, loss, o);
    const int t = threadIdx.x;
    if ((t & 31) == 0) wsum[t >> 5] = loss;
    __syncthreads();
    if (t < 32) {
        float x = (t < 8) ? wsum[t] : 0.f;
#pragma unroll
        for (int o = 4; o; o >>= 1) x += __shfl_xor_sync(0xFFFFFFFFu, x, o);
        if (t == 0) atomicAdd(out, x * (1.0f / (float)N_ROWS));
    }
}

// ---------------- Launch ----------------
extern "C" void kernel_launch(void* const* d_in, const int* in_sizes, int n_in,
                              void* d_out, int out_size) {
    const float* emb       = (const float*)d_in[0];
    const float* centers   = (const float*)d_in[1];
    const long long* label = (const long long*)d_in[2];
    float* out             = (float*)d_out;

    cudaFuncSetAttribute(gemm_chunk_kernel, cudaFuncAttributeMaxDynamicSharedMemorySize, SMEM_DYN);

    prep_centers_kernel<<<K_CENT, 256>>>(centers, out);
    prep_emb_kernel<<<N_ROWS / 8, 256>>>(emb);
    gemm_chunk_kernel<<<(N_ROWS / TILE_M) * NCHUNK, 512, SMEM_DYN>>>(label);
    finalize_kernel<<<N_ROWS / 256, 256>>>(out);
}

// round 7
// speedup vs baseline: 1.4216x; 1.0006x over previous
#include <cuda_runtime.h>
#include <cuda_bf16.h>
#include <cstdint>

#define N_ROWS   65536
#define K_CENT   512
#define D_DIM    1024
#define TILE_M   128
#define CH_N     128          // centers per chunk
#define NCHUNK   4
#define KSLAB    64
#define NSLABS   (D_DIM / KSLAB)   // 16
#define TAU_F    0.1f
#define EPS_F    1e-8f

// Normalized centers in bf16 (1/||c|| folded in), row-major [K_CENT][D_DIM]
__device__ __align__(16) __nv_bfloat16 g_cbf[K_CENT * D_DIM];
// Normalized embeddings in bf16 with 1/(||e||*tau) folded in, [N_ROWS][D_DIM]
__device__ __align__(16) __nv_bfloat16 g_ebf[(size_t)N_ROWS * D_DIM];
// Per-chunk partial softmax stats
__device__ float g_pm[NCHUNK * N_ROWS];
__device__ float g_ps[NCHUNK * N_ROWS];
__device__ float g_plv[NCHUNK * N_ROWS];

// ---------------- helpers ----------------
__device__ __forceinline__ uint32_t smem_u32(const void* p) {
    uint32_t a;
    asm("{ .reg .u64 t; cvta.to.shared.u64 t, %1; cvt.u32.u64 %0, t; }" : "=r"(a) : "l"(p));
    return a;
}
#define SWZ(o) ((o) ^ ((((uint32_t)(o)) >> 3) & 0x70u))

__device__ __forceinline__ void cp16(uint32_t dst, const void* src) {
    asm volatile("cp.async.cg.shared.global [%0], [%1], 16;"
                 :: "r"(dst), "l"(__cvta_generic_to_global(src)) : "memory");
}
#define CP_COMMIT() asm volatile("cp.async.commit_group;" ::: "memory")
#define CP_WAIT1()  asm volatile("cp.async.wait_group 1;" ::: "memory")

__device__ __forceinline__ void ldsm4(uint32_t* r, uint32_t addr) {
    asm volatile("ldmatrix.sync.aligned.m8n8.x4.shared.b16 {%0,%1,%2,%3}, [%4];"
                 : "=r"(r[0]), "=r"(r[1]), "=r"(r[2]), "=r"(r[3]) : "r"(addr));
}

__device__ __forceinline__ void mma16816(float* d, const uint32_t* a,
                                         uint32_t b0, uint32_t b1) {
    asm volatile(
        "mma.sync.aligned.m16n8k16.row.col.f32.bf16.bf16.f32 "
        "{%0,%1,%2,%3}, {%4,%5,%6,%7}, {%8,%9}, {%0,%1,%2,%3};"
        : "+f"(d[0]), "+f"(d[1]), "+f"(d[2]), "+f"(d[3])
        : "r"(a[0]), "r"(a[1]), "r"(a[2]), "r"(a[3]), "r"(b0), "r"(b1));
}

__device__ __forceinline__ uint32_t pk(float x, float y) {
    __nv_bfloat162 h = __floats2bfloat162_rn(x, y);
    return *reinterpret_cast<uint32_t*>(&h);
}

// ---------------- Kernel 1: normalize centers -> bf16, zero out ----------------
__global__ void __launch_bounds__(256) prep_centers_kernel(const float* __restrict__ centers,
                                                           float* __restrict__ out) {
    __shared__ float wss[8];
    const int row = blockIdx.x;
    const int t = threadIdx.x;

    float4 v = reinterpret_cast<const float4*>(centers + (size_t)row * D_DIM)[t];
    float ss = v.x * v.x + v.y * v.y + v.z * v.z + v.w * v.w;
#pragma unroll
    for (int o = 16; o; o >>= 1) ss += __shfl_xor_sync(0xFFFFFFFFu, ss, o);
    if ((t & 31) == 0) wss[t >> 5] = ss;
    __syncthreads();
    if (t < 32) {
        float x = (t < 8) ? wss[t] : 0.f;
#pragma unroll
        for (int o = 4; o; o >>= 1) x += __shfl_xor_sync(0xFFFFFFFFu, x, o);
        if (t == 0) wss[0] = x;
    }
    __syncthreads();
    const float sc = 1.0f / fmaxf(sqrtf(wss[0]), EPS_F);

    __nv_bfloat162* orow = reinterpret_cast<__nv_bfloat162*>(g_cbf + (size_t)row * D_DIM);
    orow[t * 2]     = __floats2bfloat162_rn(v.x * sc, v.y * sc);
    orow[t * 2 + 1] = __floats2bfloat162_rn(v.z * sc, v.w * sc);

    if (row == 0 && t == 0) out[0] = 0.f;
}

// ---------------- Kernel 1b: embeddings -> bf16 with 1/(||e||*tau) folded ----------------
__global__ void __launch_bounds__(256) prep_emb_kernel(const float* __restrict__ emb) {
    const int lane = threadIdx.x & 31;
    const int wrp  = threadIdx.x >> 5;
    const int row  = blockIdx.x * 8 + wrp;

    const float4* src = reinterpret_cast<const float4*>(emb + (size_t)row * D_DIM);
    float4 v[8];
    float ss = 0.f;
#pragma unroll
    for (int j = 0; j < 8; ++j) {
        v[j] = src[lane + j * 32];
        ss += v[j].x * v[j].x + v[j].y * v[j].y + v[j].z * v[j].z + v[j].w * v[j].w;
    }
#pragma unroll
    for (int o = 16; o; o >>= 1) ss += __shfl_xor_sync(0xFFFFFFFFu, ss, o);
    const float sc = 1.0f / (fmaxf(sqrtf(ss), EPS_F) * TAU_F);

    uint2* dst = reinterpret_cast<uint2*>(g_ebf + (size_t)row * D_DIM);
#pragma unroll
    for (int j = 0; j < 8; ++j) {
        uint2 o;
        o.x = pk(v[j].x * sc, v[j].y * sc);
        o.y = pk(v[j].z * sc, v[j].w * sc);
        dst[lane + j * 32] = o;
    }
}

// ---------------- Kernel 2: GEMM chunk, 256 thr, 2 CTAs/SM ----------------
// grid = 2048: mtile = bid>>2 (128 rows), chunk = bid&3 (128 centers)
// 8 warps, 2(m) x 4(n): warp tile 64 rows x 32 cols, acc 64 regs
// SMEM (1024-aligned base), 3-stage:
//   A 3 x 16384 @ 0, B 3 x 16384 @ 49152 -> 98304; stats after.
#define A_STG     16384u
#define B_STG     16384u
#define OFF_A     0u
#define OFF_B     49152u
#define OFF_MM    98304u          // 512 f
#define OFF_MS    100352u
#define OFF_MLV   102400u         // end 104448
#define SMEM_DYN  (104448 + 1024)

__global__ void __launch_bounds__(256, 2)
gemm_chunk_kernel(const long long* __restrict__ labels) {
    extern __shared__ uint8_t dyn[];
    const uint32_t sb = smem_u32(dyn);
    const uint32_t base = (sb + 1023u) & ~1023u;
    uint8_t* gbase = dyn + (base - sb);

    float* sm_m  = reinterpret_cast<float*>(gbase + OFF_MM);
    float* sm_s  = reinterpret_cast<float*>(gbase + OFF_MS);
    float* sm_lv = reinterpret_cast<float*>(gbase + OFF_MLV);

    const int t     = threadIdx.x;
    const int lane  = t & 31;
    const int wid   = t >> 5;
    const int wm    = wid & 1;    // 64-row slice
    const int wn    = wid >> 1;   // 32-col slice
    const int bid   = blockIdx.x;
    const int mtile = bid >> 2;
    const int chunk = bid & 3;
    const int row0  = mtile * TILE_M;

    // loader mapping: 16B chunk c = t + i*256 -> row = (t>>3) + i*32, off8 = t&7
    const int lr = t >> 3, lo = t & 7;
    uint32_t l_sw[4];
#pragma unroll
    for (int i = 0; i < 4; ++i)
        l_sw[i] = SWZ((uint32_t)((lr + i * 32) * 128 + lo * 16));
    const __nv_bfloat16* agp = g_ebf + (size_t)(row0 + lr) * D_DIM + lo * 8;
    const __nv_bfloat16* bgp = g_cbf + (size_t)(chunk * CH_N + lr) * D_DIM + lo * 8;

    auto issue = [&](int kb, int stg) {
        const uint32_t Ad = base + OFF_A + (uint32_t)stg * A_STG;
        const uint32_t Bd = base + OFF_B + (uint32_t)stg * B_STG;
        const __nv_bfloat16* sa = agp + kb * KSLAB;
        const __nv_bfloat16* sb2 = bgp + kb * KSLAB;
#pragma unroll
        for (int i = 0; i < 4; ++i) cp16(Ad + l_sw[i], sa + (size_t)(i * 32) * D_DIM);
#pragma unroll
        for (int i = 0; i < 4; ++i) cp16(Bd + l_sw[i], sb2 + (size_t)(i * 32) * D_DIM);
    };

    float acc[4][4][4];
#pragma unroll
    for (int am = 0; am < 4; ++am)
#pragma unroll
        for (int an = 0; an < 4; ++an)
#pragma unroll
            for (int k = 0; k < 4; ++k) acc[am][an][k] = 0.f;

    // ---- prologue: stages 0,1 in flight ----
    issue(0, 0); CP_COMMIT();
    issue(1, 1); CP_COMMIT();

    const int rlow = lane & 15;
    const int bhi  = (lane >> 4) * 16;

#pragma unroll 1
    for (int kb = 0; kb < NSLABS; ++kb) {
        const int stg = kb % 3;
        const uint32_t Ab = base + OFF_A + (uint32_t)stg * A_STG;
        const uint32_t Bb = base + OFF_B + (uint32_t)stg * B_STG;

        CP_WAIT1();              // slab kb resident (kb+1 may be pending)
        __syncthreads();         // all warps done with slab kb-1 -> stage (kb+2)%3 free

        if (kb + 2 < NSLABS) issue(kb + 2, (kb + 2) % 3);
        CP_COMMIT();

#pragma unroll
        for (int ks = 0; ks < 4; ++ks) {
            const uint32_t byt = (uint32_t)(ks * 32 + bhi);
            uint32_t af[4][4], bf[2][4];
#pragma unroll
            for (int am = 0; am < 4; ++am)
                ldsm4(af[am], Ab + SWZ((uint32_t)((wm * 64 + am * 16 + rlow) * 128) + byt));
#pragma unroll
            for (int p = 0; p < 2; ++p)
                ldsm4(bf[p], Bb + SWZ((uint32_t)((wn * 32 + p * 16 + rlow) * 128) + byt));
#pragma unroll
            for (int am = 0; am < 4; ++am)
#pragma unroll
                for (int p = 0; p < 2; ++p) {
                    mma16816(acc[am][2 * p],     af[am], bf[p][0], bf[p][2]);
                    mma16816(acc[am][2 * p + 1], af[am], bf[p][1], bf[p][3]);
                }
        }
    }
    __syncthreads();

    // ---- per-warp partial softmax over its 32 cols (scale pre-folded) ----
    const int ql = lane >> 2, qc = lane & 3;
#pragma unroll
    for (int am = 0; am < 4; ++am) {
#pragma unroll
        for (int h = 0; h < 2; ++h) {
            const int r = wm * 64 + am * 16 + ql + 8 * h;
            const int lc = (int)labels[row0 + r];

            float m = -1e30f;
            float v[8];
#pragma unroll
            for (int an = 0; an < 4; ++an)
#pragma unroll
                for (int e = 0; e < 2; ++e) {
                    float x = acc[am][an][2 * h + e];
                    v[an * 2 + e] = x;
                    m = fmaxf(m, x);
                }
            m = fmaxf(m, __shfl_xor_sync(0xFFFFFFFFu, m, 1));
            m = fmaxf(m, __shfl_xor_sync(0xFFFFFFFFu, m, 2));

            float s = 0.f, lv = 0.f;
#pragma unroll
            for (int an = 0; an < 4; ++an)
#pragma unroll
                for (int e = 0; e < 2; ++e) {
                    s += __expf(v[an * 2 + e] - m);
                    const int col = chunk * CH_N + wn * 32 + an * 8 + qc * 2 + e;
                    if (col == lc) lv = v[an * 2 + e];
                }
            s  += __shfl_xor_sync(0xFFFFFFFFu, s, 1);
            s  += __shfl_xor_sync(0xFFFFFFFFu, s, 2);
            lv += __shfl_xor_sync(0xFFFFFFFFu, lv, 1);
            lv += __shfl_xor_sync(0xFFFFFFFFu, lv, 2);

            if (qc == 0) {
                sm_m[wn * 128 + r]  = m;
                sm_s[wn * 128 + r]  = s;
                sm_lv[wn * 128 + r] = lv;
            }
        }
    }
    __syncthreads();

    // ---- merge 4 warp-columns, write chunk partials ----
    if (t < TILE_M) {
        float M = -1e30f;
#pragma unroll
        for (int w = 0; w < 4; ++w) M = fmaxf(M, sm_m[w * 128 + t]);
        float S = 0.f, LV = 0.f;
#pragma unroll
        for (int w = 0; w < 4; ++w) {
            S  += sm_s[w * 128 + t] * __expf(sm_m[w * 128 + t] - M);
            LV += sm_lv[w * 128 + t];
        }
        const int gr = row0 + t;
        g_pm[chunk * N_ROWS + gr]  = M;
        g_ps[chunk * N_ROWS + gr]  = S;
        g_plv[chunk * N_ROWS + gr] = LV;
    }
}

// ---------------- Kernel 3: finalize (merge 4 chunks) ----------------
__global__ void __launch_bounds__(256) finalize_kernel(float* __restrict__ out) {
    __shared__ float wsum[8];
    const int r = blockIdx.x * 256 + threadIdx.x;

    float M = -1e30f;
#pragma unroll
    for (int c = 0; c < NCHUNK; ++c) M = fmaxf(M, g_pm[c * N_ROWS + r]);
    float S = 0.f, LV = 0.f;
#pragma unroll
    for (int c = 0; c < NCHUNK; ++c) {
        S  += g_ps[c * N_ROWS + r] * expf(g_pm[c * N_ROWS + r] - M);
        LV += g_plv[c * N_ROWS + r];
    }
    float loss = (M + logf(S)) - LV;

#pragma unroll
    for (int o = 16; o; o >>= 1) loss += __shfl_xor_sync(0xFFFFFFFFu, loss, o);
    const int t = threadIdx.x;
    if ((t & 31) == 0) wsum[t >> 5] = loss;
    __syncthreads();
    if (t < 32) {
        float x = (t < 8) ? wsum[t] : 0.f;
#pragma unroll
        for (int o = 4; o; o >>= 1) x += __shfl_xor_sync(0xFFFFFFFFu, x, o);
        if (t == 0) atomicAdd(out, x * (1.0f / (float)N_ROWS));
    }
}

// ---------------- Launch ----------------
extern "C" void kernel_launch(void* const* d_in, const int* in_sizes, int n_in,
                              void* d_out, int out_size) {
    const float* emb       = (const float*)d_in[0];
    const float* centers   = (const float*)d_in[1];
    const long long* label = (const long long*)d_in[2];
    float* out             = (float*)d_out;

    cudaFuncSetAttribute(gemm_chunk_kernel, cudaFuncAttributeMaxDynamicSharedMemorySize, SMEM_DYN);

    prep_centers_kernel<<<K_CENT, 256>>>(centers, out);
    prep_emb_kernel<<<N_ROWS / 8, 256>>>(emb);
    gemm_chunk_kernel<<<(N_ROWS / TILE_M) * NCHUNK, 256, SMEM_DYN>>>(label);
    finalize_kernel<<<N_ROWS / 256, 256>>>(out);
}